// round 15
// baseline (speedup 1.0000x reference)
#include <cuda_runtime.h>
#include <cuda_fp16.h>
#include <cstdint>

#define NB 2
#define NN 20000
#define DD 256
#define EE 320000
#define NL 2
#define ALPHA 0.2f

#define TM 128
#define TN 128
#define KC 32
#define NST (DD / KC)                 // 8
#define NTILES ((NN + TM - 1) / TM)   // 157
#define ROWB 80                       // 64B data + 16B pad
#define TILEB (128 * ROWB)            // 10240
#define STAGEB (2 * TILEB)            // 20480 (A, B)
#define NBUF 3
#define SMEMB (NBUF * STAGEB)         // 61440 (3-stage)
#define NNODES (NB * NN)              // 40000
#define NEDGES (NB * EE)              // 640000

// ---------------- device scratch ----------------
__device__ __half g_h[NB * NN * DD];          // h in fp16
__device__ float g_sqL[2 * NNODES];
__device__ float g_snA[NNODES], g_snB[NNODES];
__device__ float g_wa1[2 * DD], g_wa2[2 * DD];
__device__ __half g_ah[NB * NN * DD];         // activation fp16
__device__ __half g_wbh[2 * DD * DD];         // W^T fp16, per layer
// CSR
__device__ int g_deg [NNODES];
__device__ int g_eoff[NNODES + 1];
__device__ int g_ecur[NNODES];
__device__ int g_edst[NEDGES];

// ---------------- helpers ----------------
__device__ __forceinline__ uint32_t smem_u32(const void* p) {
    uint32_t a;
    asm("{ .reg .u64 t; cvta.to.shared.u64 t, %1; cvt.u32.u64 %0, t; }" : "=r"(a) : "l"(p));
    return a;
}
__device__ __forceinline__ void cp16(uint32_t dst, const void* src, int bytes) {
    asm volatile("cp.async.cg.shared.global [%0], [%1], 16, %2;"
                 :: "r"(dst), "l"(src), "r"(bytes) : "memory");
}
#define CP_COMMIT() asm volatile("cp.async.commit_group;" ::: "memory")
#define CP_WAIT(n)  asm volatile("cp.async.wait_group %0;" :: "n"(n) : "memory")
__device__ __forceinline__ void ldx4(uint32_t r[4], uint32_t addr) {
    asm volatile("ldmatrix.sync.aligned.m8n8.x4.shared.b16 {%0,%1,%2,%3}, [%4];"
                 : "=r"(r[0]), "=r"(r[1]), "=r"(r[2]), "=r"(r[3]) : "r"(addr));
}
__device__ __forceinline__ void ldx2(uint32_t r[2], uint32_t addr) {
    asm volatile("ldmatrix.sync.aligned.m8n8.x2.shared.b16 {%0,%1}, [%2];"
                 : "=r"(r[0]), "=r"(r[1]) : "r"(addr));
}
__device__ __forceinline__ void mma16816h(float c[4], const uint32_t a[4], const uint32_t b[2]) {
    asm volatile("mma.sync.aligned.m16n8k16.row.col.f32.f16.f16.f32 "
                 "{%0,%1,%2,%3}, {%4,%5,%6,%7}, {%8,%9}, {%0,%1,%2,%3};"
                 : "+f"(c[0]), "+f"(c[1]), "+f"(c[2]), "+f"(c[3])
                 : "r"(a[0]), "r"(a[1]), "r"(a[2]), "r"(a[3]), "r"(b[0]), "r"(b[1]));
}
__device__ __forceinline__ void fma8(float acc[8], uint4 u, float w) {
    const half2* hp = (const half2*)&u;
    #pragma unroll
    for (int k = 0; k < 4; k++) {
        float2 f = __half22float2(hp[k]);
        acc[2 * k]     += w * f.x;
        acc[2 * k + 1] += w * f.y;
    }
}

// ============================ CSR construction ============================
__global__ void hist(const int* __restrict__ edges) {
    int i = blockIdx.x * blockDim.x + threadIdx.x;
    if (i >= NEDGES) return;
    int b = i / EE, e = i - b * EE;
    int src = edges[(size_t)b * 2 * EE + e];
    atomicAdd(&g_deg[b * NN + src], 1);
}
__global__ void scan_deg() {
    __shared__ int s[1024];
    const int base = threadIdx.x * 40;
    int loc[40];
    int run = 0;
    #pragma unroll
    for (int j = 0; j < 40; j++) {
        int i = base + j;
        int d = (i < NNODES) ? g_deg[i] : 0;
        run += d;
        loc[j] = run;
    }
    s[threadIdx.x] = run;
    __syncthreads();
    for (int o = 1; o < 1024; o <<= 1) {
        int add = (threadIdx.x >= o) ? s[threadIdx.x - o] : 0;
        __syncthreads();
        s[threadIdx.x] += add;
        __syncthreads();
    }
    int excl = threadIdx.x ? s[threadIdx.x - 1] : 0;
    int prev = excl;
    #pragma unroll
    for (int j = 0; j < 40; j++) {
        int i = base + j;
        if (i < NNODES) {
            g_ecur[i] = prev;
            g_eoff[i + 1] = excl + loc[j];
            prev = excl + loc[j];
        }
    }
    if (threadIdx.x == 0) g_eoff[0] = 0;
}
__global__ void scatter(const int* __restrict__ edges) {
    int i = blockIdx.x * blockDim.x + threadIdx.x;
    if (i >= NEDGES) return;
    int b = i / EE, e = i - b * EE;
    const int* eb = edges + (size_t)b * 2 * EE;
    int src = eb[e], dst = eb[EE + e];
    int pos = atomicAdd(&g_ecur[b * NN + src], 1);
    g_edst[pos] = dst;
}

// ============================ prep kernels ============================
__global__ void conv_half(const float* __restrict__ src) {
    int i = (blockIdx.x * blockDim.x + threadIdx.x) * 4;
    if (i >= NB * NN * DD) return;
    float4 v = *(const float4*)(src + i);
    __half h[4];
    h[0] = __float2half_rn(v.x); h[1] = __float2half_rn(v.y);
    h[2] = __float2half_rn(v.z); h[3] = __float2half_rn(v.w);
    *(uint2*)(g_ah + i) = *(uint2*)h;
}

__global__ void wa_all(const float* __restrict__ W, const float* __restrict__ a) {
    int k = blockIdx.x, l = blockIdx.y, t = threadIdx.x;
    const float* Wl = W + (size_t)l * DD * DD;
    const float* al = a + (size_t)l * 2 * DD;
    float w = Wl[k * DD + t];
    float v1 = w * al[t];
    float v2 = w * al[DD + t];
    #pragma unroll
    for (int o = 16; o > 0; o >>= 1) {
        v1 += __shfl_down_sync(0xFFFFFFFFu, v1, o);
        v2 += __shfl_down_sync(0xFFFFFFFFu, v2, o);
    }
    __shared__ float s1[8], s2[8];
    int wp = t >> 5, ln = t & 31;
    if (ln == 0) { s1[wp] = v1; s2[wp] = v2; }
    __syncthreads();
    if (t == 0) {
        float a1 = 0.f, a2 = 0.f;
        #pragma unroll
        for (int i = 0; i < 8; i++) { a1 += s1[i]; a2 += s2[i]; }
        g_wa1[l * DD + k] = a1;
        g_wa2[l * DD + k] = a2;
    }
}

__global__ void prep_w(const float* __restrict__ W) {
    int n = blockIdx.x, l = blockIdx.y, k = threadIdx.x;
    float v = W[(size_t)l * DD * DD + k * DD + n];
    g_wbh[(size_t)l * DD * DD + n * DD + k] = __float2half_rn(v);
}

__global__ void score_all(const float* __restrict__ xq, const float* __restrict__ x0) {
    int node = blockIdx.x;
    int t = threadIdx.x;
    size_t idx = (size_t)node * DD + t;
    float q = xq[idx], x = x0[idx];
    float v0 = q * g_wa1[t];
    float v1 = q * g_wa1[DD + t];
    float v2 = x * g_wa2[t];
    #pragma unroll
    for (int o = 16; o > 0; o >>= 1) {
        v0 += __shfl_down_sync(0xFFFFFFFFu, v0, o);
        v1 += __shfl_down_sync(0xFFFFFFFFu, v1, o);
        v2 += __shfl_down_sync(0xFFFFFFFFu, v2, o);
    }
    __shared__ float s0[8], s1[8], s2[8];
    int w = t >> 5, ln = t & 31;
    if (ln == 0) { s0[w] = v0; s1[w] = v1; s2[w] = v2; }
    __syncthreads();
    if (t == 0) {
        float a0 = 0.f, a1 = 0.f, a2 = 0.f;
        #pragma unroll
        for (int i = 0; i < 8; i++) { a0 += s0[i]; a1 += s1[i]; a2 += s2[i]; }
        g_sqL[node] = a0;
        g_sqL[NNODES + node] = a1;
        g_snA[node] = a2;
    }
}

// ============================ GEMM (fp16, cp.async 3-stage, 1 sync/chunk) ============================
__global__ void __launch_bounds__(256, 2)
gemm_mma(int layer) {
    extern __shared__ char smem[];
    const int tid = threadIdx.x;
    const int wid = tid >> 5, lane = tid & 31;
    const int wm = wid & 3, wn = wid >> 2;

    const int b = blockIdx.z;
    const size_t boff = (size_t)b * NN * DD;
    const __half* A = g_ah + boff;
    const __half* B = g_wbh + (size_t)layer * DD * DD;
    __half* C = g_h + boff;
    const int row0 = blockIdx.x * TM;
    const int col0 = blockIdx.y * TN;

    const uint32_t sb = smem_u32(smem);

    const int crow0 = tid >> 2, cq0 = tid & 3;
    const int crow1 = (tid + 256) >> 2, cq1 = tid & 3;
    const int aok0 = (row0 + crow0) < NN ? 16 : 0;
    const int aok1 = (row0 + crow1) < NN ? 16 : 0;
    const uint32_t so0 = (uint32_t)(crow0 * ROWB + cq0 * 16);
    const uint32_t so1 = (uint32_t)(crow1 * ROWB + cq1 * 16);
    const size_t sa0 = (size_t)(row0 + crow0) * DD + cq0 * 8;
    const size_t sa1 = (size_t)(row0 + crow1) * DD + cq1 * 8;
    const size_t sb0 = (size_t)(col0 + crow0) * DD + cq0 * 8;
    const size_t sb1 = (size_t)(col0 + crow1) * DD + cq1 * 8;

    auto issue = [&](int c) {
        uint32_t st = sb + (uint32_t)(c % NBUF) * STAGEB;
        int k0 = c * KC;
        cp16(st + so0,         A + sa0 + k0, aok0);
        cp16(st + so1,         A + sa1 + k0, aok1);
        cp16(st + TILEB + so0, B + sb0 + k0, 16);
        cp16(st + TILEB + so1, B + sb1 + k0, 16);
        CP_COMMIT();
    };

    float acc[2][8][4];
    #pragma unroll
    for (int i = 0; i < 2; i++)
        #pragma unroll
        for (int j = 0; j < 8; j++)
            #pragma unroll
            for (int q = 0; q < 4; q++) acc[i][j][q] = 0.f;

    const uint32_t aob = (uint32_t)((wm * 32 + (lane & 15)) * ROWB + (lane >> 4) * 16);
    const uint32_t bob = (uint32_t)((wn * 64 + (lane & 7)) * ROWB + ((lane >> 3) & 1) * 16);

    issue(0);
    issue(1);
    for (int c = 0; c < NST; c++) {
        // group c must be complete; issued through min(c+1, NST-1)
        if (c + 1 < NST) CP_WAIT(1); else CP_WAIT(0);
        __syncthreads();               // all warps done computing chunk c-1
        if (c + 2 < NST) issue(c + 2); // safe: buffer (c+2)%3 == (c-1)%3 is free

        uint32_t st = sb + (uint32_t)(c % NBUF) * STAGEB;
        #pragma unroll
        for (int ks = 0; ks < 2; ks++) {
            uint32_t ao = st + aob + ks * 32;
            uint32_t bo = st + bob + ks * 32;
            uint32_t av[2][4];
            #pragma unroll
            for (int mt = 0; mt < 2; mt++)
                ldx4(av[mt], ao + mt * 16 * ROWB);
            #pragma unroll
            for (int nt = 0; nt < 8; nt++) {
                uint32_t bh[2];
                ldx2(bh, TILEB + bo + nt * 8 * ROWB);
                #pragma unroll
                for (int mt = 0; mt < 2; mt++)
                    mma16816h(acc[mt][nt], av[mt], bh);
            }
        }
    }

    const int g = lane >> 2, t2 = (lane & 3) * 2;
    #pragma unroll
    for (int mt = 0; mt < 2; mt++) {
        int r = row0 + wm * 32 + mt * 16 + g;
        #pragma unroll
        for (int nt = 0; nt < 8; nt++) {
            int col = col0 + wn * 64 + nt * 8 + t2;
            if (r < NN)
                *(half2*)(C + (size_t)r * DD + col) =
                    __floats2half2_rn(acc[mt][nt][0], acc[mt][nt][1]);
            if (r + 8 < NN)
                *(half2*)(C + (size_t)(r + 8) * DD + col) =
                    __floats2half2_rn(acc[mt][nt][2], acc[mt][nt][3]);
        }
    }
}

// ============================ fused edge aggregate (fp16 h, 8 warp-groups) ============================
__global__ void __launch_bounds__(256)
edge_agg(const float* __restrict__ nodes, float* __restrict__ out,
         const float* __restrict__ sqp, const float* __restrict__ snp,
         float* __restrict__ sn_out, const float* __restrict__ wa2n, int last) {
    __shared__ float ws[256];
    __shared__ int   sdst[256];
    __shared__ float red[8 * 256];
    __shared__ float rsg[8];
    __shared__ float red8[8];

    const int node = blockIdx.x;
    const int b = node / NN;
    const int t = threadIdx.x;
    const int g = t >> 5;
    const int c8 = t & 31;
    const int off = g_eoff[node], end = g_eoff[node + 1];
    const float sq = sqp[node];
    const uint4* __restrict__ hb = (const uint4*)(g_h + (size_t)b * NN * DD);
    const float* __restrict__ snb = snp + b * NN;

    float acc[8];
    #pragma unroll
    for (int k = 0; k < 8; k++) acc[k] = 0.f;
    float rs = 0.f;

    for (int base = off; base < end; base += 256) {
        int m = min(256, end - base);
        if (t < m) {
            int dst = g_edst[base + t];
            sdst[t] = dst;
            float s = sq + snb[dst];
            float lr = (s >= 0.f) ? s : ALPHA * s;
            ws[t] = __expf(-lr);
        }
        __syncthreads();
        int j = g;
        for (; j + 8 < m; j += 16) {
            float w0 = ws[j], w1 = ws[j + 8];
            uint4 h0 = hb[(size_t)sdst[j] * 32 + c8];
            uint4 h1 = hb[(size_t)sdst[j + 8] * 32 + c8];
            fma8(acc, h0, w0);
            fma8(acc, h1, w1);
            rs += w0 + w1;
        }
        for (; j < m; j += 8) {
            float w0 = ws[j];
            uint4 h0 = hb[(size_t)sdst[j] * 32 + c8];
            fma8(acc, h0, w0);
            rs += w0;
        }
        __syncthreads();
    }

    #pragma unroll
    for (int k = 0; k < 8; k++) red[g * 256 + c8 * 8 + k] = acc[k];
    if (c8 == 0) rsg[g] = rs;
    __syncthreads();

    float v_raw = 0.f;
    #pragma unroll
    for (int gg = 0; gg < 8; gg++) v_raw += red[gg * 256 + t];
    float rstot = rsg[0] + rsg[1] + rsg[2] + rsg[3] + rsg[4] + rsg[5] + rsg[6] + rsg[7];
    float v = (rstot == 0.f) ? 0.f : v_raw / rstot;
    size_t idx = (size_t)node * DD + t;

    if (last) {
        out[idx] = v + nodes[idx];
    } else {
        g_ah[idx] = __float2half_rn(v);
        float p = v * wa2n[t];
        #pragma unroll
        for (int o = 16; o > 0; o >>= 1)
            p += __shfl_down_sync(0xFFFFFFFFu, p, o);
        int w = t >> 5, ln = t & 31;
        if (ln == 0) red8[w] = p;
        __syncthreads();
        if (t == 0) {
            float S = 0.f;
            #pragma unroll
            for (int i = 0; i < 8; i++) S += red8[i];
            sn_out[node] = S;
        }
    }
}

// ---------------------------------------------------------------------------
extern "C" void kernel_launch(void* const* d_in, const int* in_sizes, int n_in,
                              void* d_out, int out_size) {
    const float* nodes  = (const float*)d_in[0];
    const float* nodesq = (const float*)d_in[1];
    const float* W      = (const float*)d_in[2];
    const float* a      = (const float*)d_in[3];
    const int*   edges  = (const int*)d_in[4];
    float* out = (float*)d_out;

    static cudaStream_t s1 = nullptr, s2 = nullptr;
    static cudaEvent_t evFork = nullptr, evW = nullptr, evScore = nullptr, evConv = nullptr;
    if (!s1) {
        cudaStreamCreateWithFlags(&s1, cudaStreamNonBlocking);
        cudaStreamCreateWithFlags(&s2, cudaStreamNonBlocking);
        cudaEventCreateWithFlags(&evFork,  cudaEventDisableTiming);
        cudaEventCreateWithFlags(&evW,     cudaEventDisableTiming);
        cudaEventCreateWithFlags(&evScore, cudaEventDisableTiming);
        cudaEventCreateWithFlags(&evConv,  cudaEventDisableTiming);
        cudaFuncSetAttribute(gemm_mma, cudaFuncAttributeMaxDynamicSharedMemorySize, SMEMB);
    }

    float *sqL, *snA, *snB, *wa2;
    int* degp;
    cudaGetSymbolAddress((void**)&sqL, g_sqL);
    cudaGetSymbolAddress((void**)&snA, g_snA);
    cudaGetSymbolAddress((void**)&snB, g_snB);
    cudaGetSymbolAddress((void**)&wa2, g_wa2);
    cudaGetSymbolAddress((void**)&degp, g_deg);

    dim3 ggrid(NTILES, DD / TN, NB);

    // ---- fork ----
    cudaEventRecord(evFork, 0);
    cudaStreamWaitEvent(s1, evFork, 0);
    cudaStreamWaitEvent(s2, evFork, 0);

    // s1: CSR build then scores
    cudaMemsetAsync(degp, 0, NNODES * sizeof(int), s1);
    hist<<<(NEDGES + 255) / 256, 256, 0, s1>>>(edges);
    scan_deg<<<1, 1024, 0, s1>>>();
    scatter<<<(NEDGES + 255) / 256, 256, 0, s1>>>(edges);

    // s2: activation conversion (one launch, both batches)
    conv_half<<<(NB * NN * DD / 4 + 255) / 256, 256, 0, s2>>>(nodes);
    cudaEventRecord(evConv, s2);

    // main: wa -> (score dependency), prep_w
    wa_all<<<dim3(DD, 2), 256>>>(W, a);
    cudaEventRecord(evW, 0);
    prep_w<<<dim3(DD, 2), DD>>>(W);

    cudaStreamWaitEvent(s1, evW, 0);
    score_all<<<NNODES, 256, 0, s1>>>(nodesq, nodes);
    cudaEventRecord(evScore, s1);

    // ---- serial chain ----
    cudaStreamWaitEvent(0, evConv, 0);
    gemm_mma<<<ggrid, 256, SMEMB>>>(0);
    cudaStreamWaitEvent(0, evScore, 0);
    edge_agg<<<NNODES, 256>>>(nodes, out, sqL, snA, snB, wa2 + DD, 0);
    gemm_mma<<<ggrid, 256, SMEMB>>>(1);
    edge_agg<<<NNODES, 256>>>(nodes, out, sqL + NNODES, snB, nullptr, nullptr, 1);
}

// round 16
// speedup vs baseline: 1.5238x; 1.5238x over previous
#include <cuda_runtime.h>
#include <cuda_fp16.h>
#include <cstdint>

#define NB 2
#define NN 20000
#define DD 256
#define EE 320000
#define NL 2
#define ALPHA 0.2f

#define TM 128
#define TN 128
#define KC 32
#define NST (DD / KC)                 // 8
#define NTILES ((NN + TM - 1) / TM)   // 157
#define ROWB 80                       // 64B data + 16B pad
#define TILEB (128 * ROWB)            // 10240
#define STAGEB (2 * TILEB)            // 20480 (A, B)
#define NBUF 3
#define SMEMB (NBUF * STAGEB)         // 61440 (3-stage)
#define NNODES (NB * NN)              // 40000
#define NEDGES (NB * EE)              // 640000

// ---------------- device scratch ----------------
__device__ __half g_h[NB * NN * DD];          // h in fp16
__device__ float g_sqL[2 * NNODES];
__device__ float g_snA[NNODES], g_snB[NNODES];
__device__ float g_wa1[2 * DD], g_wa2[2 * DD];
__device__ __half g_ah[NB * NN * DD];         // activation fp16
__device__ __half g_wbh[2 * DD * DD];         // W^T fp16, per layer
// CSR
__device__ int g_deg [NNODES];
__device__ int g_eoff[NNODES + 1];
__device__ int g_ecur[NNODES];
__device__ int g_edst[NEDGES];

// ---------------- helpers ----------------
__device__ __forceinline__ uint32_t smem_u32(const void* p) {
    uint32_t a;
    asm("{ .reg .u64 t; cvta.to.shared.u64 t, %1; cvt.u32.u64 %0, t; }" : "=r"(a) : "l"(p));
    return a;
}
__device__ __forceinline__ void cp16(uint32_t dst, const void* src, int bytes) {
    asm volatile("cp.async.cg.shared.global [%0], [%1], 16, %2;"
                 :: "r"(dst), "l"(src), "r"(bytes) : "memory");
}
#define CP_COMMIT() asm volatile("cp.async.commit_group;" ::: "memory")
#define CP_WAIT(n)  asm volatile("cp.async.wait_group %0;" :: "n"(n) : "memory")
__device__ __forceinline__ void ldx4(uint32_t r[4], uint32_t addr) {
    asm volatile("ldmatrix.sync.aligned.m8n8.x4.shared.b16 {%0,%1,%2,%3}, [%4];"
                 : "=r"(r[0]), "=r"(r[1]), "=r"(r[2]), "=r"(r[3]) : "r"(addr));
}
__device__ __forceinline__ void ldx2(uint32_t r[2], uint32_t addr) {
    asm volatile("ldmatrix.sync.aligned.m8n8.x2.shared.b16 {%0,%1}, [%2];"
                 : "=r"(r[0]), "=r"(r[1]) : "r"(addr));
}
__device__ __forceinline__ void mma16816h(float c[4], const uint32_t a[4], const uint32_t b[2]) {
    asm volatile("mma.sync.aligned.m16n8k16.row.col.f32.f16.f16.f32 "
                 "{%0,%1,%2,%3}, {%4,%5,%6,%7}, {%8,%9}, {%0,%1,%2,%3};"
                 : "+f"(c[0]), "+f"(c[1]), "+f"(c[2]), "+f"(c[3])
                 : "r"(a[0]), "r"(a[1]), "r"(a[2]), "r"(a[3]), "r"(b[0]), "r"(b[1]));
}
__device__ __forceinline__ void fma8(float acc[8], uint4 u, float w) {
    const half2* hp = (const half2*)&u;
    #pragma unroll
    for (int k = 0; k < 4; k++) {
        float2 f = __half22float2(hp[k]);
        acc[2 * k]     += w * f.x;
        acc[2 * k + 1] += w * f.y;
    }
}

// ============================ CSR construction ============================
__global__ void hist(const int* __restrict__ edges) {
    int i = blockIdx.x * blockDim.x + threadIdx.x;
    if (i >= NEDGES) return;
    int b = i / EE, e = i - b * EE;
    int src = edges[(size_t)b * 2 * EE + e];
    atomicAdd(&g_deg[b * NN + src], 1);
}
__global__ void scan_deg() {
    __shared__ int s[1024];
    const int base = threadIdx.x * 40;
    int loc[40];
    int run = 0;
    #pragma unroll
    for (int j = 0; j < 40; j++) {
        int i = base + j;
        int d = (i < NNODES) ? g_deg[i] : 0;
        run += d;
        loc[j] = run;
    }
    s[threadIdx.x] = run;
    __syncthreads();
    for (int o = 1; o < 1024; o <<= 1) {
        int add = (threadIdx.x >= o) ? s[threadIdx.x - o] : 0;
        __syncthreads();
        s[threadIdx.x] += add;
        __syncthreads();
    }
    int excl = threadIdx.x ? s[threadIdx.x - 1] : 0;
    int prev = excl;
    #pragma unroll
    for (int j = 0; j < 40; j++) {
        int i = base + j;
        if (i < NNODES) {
            g_ecur[i] = prev;
            g_eoff[i + 1] = excl + loc[j];
            prev = excl + loc[j];
        }
    }
    if (threadIdx.x == 0) g_eoff[0] = 0;
}
__global__ void scatter(const int* __restrict__ edges) {
    int i = blockIdx.x * blockDim.x + threadIdx.x;
    if (i >= NEDGES) return;
    int b = i / EE, e = i - b * EE;
    const int* eb = edges + (size_t)b * 2 * EE;
    int src = eb[e], dst = eb[EE + e];
    int pos = atomicAdd(&g_ecur[b * NN + src], 1);
    g_edst[pos] = dst;
}

// ============================ prep kernels ============================
__global__ void conv_half(const float* __restrict__ src) {
    int i = (blockIdx.x * blockDim.x + threadIdx.x) * 4;
    if (i >= NB * NN * DD) return;
    float4 v = *(const float4*)(src + i);
    __half h[4];
    h[0] = __float2half_rn(v.x); h[1] = __float2half_rn(v.y);
    h[2] = __float2half_rn(v.z); h[3] = __float2half_rn(v.w);
    *(uint2*)(g_ah + i) = *(uint2*)h;
}

__global__ void wa_all(const float* __restrict__ W, const float* __restrict__ a) {
    int k = blockIdx.x, l = blockIdx.y, t = threadIdx.x;
    const float* Wl = W + (size_t)l * DD * DD;
    const float* al = a + (size_t)l * 2 * DD;
    float w = Wl[k * DD + t];
    float v1 = w * al[t];
    float v2 = w * al[DD + t];
    #pragma unroll
    for (int o = 16; o > 0; o >>= 1) {
        v1 += __shfl_down_sync(0xFFFFFFFFu, v1, o);
        v2 += __shfl_down_sync(0xFFFFFFFFu, v2, o);
    }
    __shared__ float s1[8], s2[8];
    int wp = t >> 5, ln = t & 31;
    if (ln == 0) { s1[wp] = v1; s2[wp] = v2; }
    __syncthreads();
    if (t == 0) {
        float a1 = 0.f, a2 = 0.f;
        #pragma unroll
        for (int i = 0; i < 8; i++) { a1 += s1[i]; a2 += s2[i]; }
        g_wa1[l * DD + k] = a1;
        g_wa2[l * DD + k] = a2;
    }
}

__global__ void prep_w(const float* __restrict__ W) {
    int n = blockIdx.x, l = blockIdx.y, k = threadIdx.x;
    float v = W[(size_t)l * DD * DD + k * DD + n];
    g_wbh[(size_t)l * DD * DD + n * DD + k] = __float2half_rn(v);
}

__global__ void score_all(const float* __restrict__ xq, const float* __restrict__ x0) {
    int node = blockIdx.x;
    int t = threadIdx.x;
    size_t idx = (size_t)node * DD + t;
    float q = xq[idx], x = x0[idx];
    float v0 = q * g_wa1[t];
    float v1 = q * g_wa1[DD + t];
    float v2 = x * g_wa2[t];
    #pragma unroll
    for (int o = 16; o > 0; o >>= 1) {
        v0 += __shfl_down_sync(0xFFFFFFFFu, v0, o);
        v1 += __shfl_down_sync(0xFFFFFFFFu, v1, o);
        v2 += __shfl_down_sync(0xFFFFFFFFu, v2, o);
    }
    __shared__ float s0[8], s1[8], s2[8];
    int w = t >> 5, ln = t & 31;
    if (ln == 0) { s0[w] = v0; s1[w] = v1; s2[w] = v2; }
    __syncthreads();
    if (t == 0) {
        float a0 = 0.f, a1 = 0.f, a2 = 0.f;
        #pragma unroll
        for (int i = 0; i < 8; i++) { a0 += s0[i]; a1 += s1[i]; a2 += s2[i]; }
        g_sqL[node] = a0;
        g_sqL[NNODES + node] = a1;
        g_snA[node] = a2;
    }
}

// ============================ GEMM (fp16, cp.async 3-stage) ============================
__global__ void __launch_bounds__(256, 2)
gemm_mma(int layer) {
    extern __shared__ char smem[];
    const int tid = threadIdx.x;
    const int wid = tid >> 5, lane = tid & 31;
    const int wm = wid & 3, wn = wid >> 2;

    const int b = blockIdx.z;
    const size_t boff = (size_t)b * NN * DD;
    const __half* A = g_ah + boff;
    const __half* B = g_wbh + (size_t)layer * DD * DD;
    __half* C = g_h + boff;
    const int row0 = blockIdx.x * TM;
    const int col0 = blockIdx.y * TN;

    const uint32_t sb = smem_u32(smem);

    const int crow0 = tid >> 2, cq0 = tid & 3;
    const int crow1 = (tid + 256) >> 2, cq1 = tid & 3;
    const int aok0 = (row0 + crow0) < NN ? 16 : 0;
    const int aok1 = (row0 + crow1) < NN ? 16 : 0;
    const uint32_t so0 = (uint32_t)(crow0 * ROWB + cq0 * 16);
    const uint32_t so1 = (uint32_t)(crow1 * ROWB + cq1 * 16);
    const size_t sa0 = (size_t)(row0 + crow0) * DD + cq0 * 8;
    const size_t sa1 = (size_t)(row0 + crow1) * DD + cq1 * 8;
    const size_t sb0 = (size_t)(col0 + crow0) * DD + cq0 * 8;
    const size_t sb1 = (size_t)(col0 + crow1) * DD + cq1 * 8;

    auto issue = [&](int c) {
        uint32_t st = sb + (uint32_t)(c % NBUF) * STAGEB;
        int k0 = c * KC;
        cp16(st + so0,         A + sa0 + k0, aok0);
        cp16(st + so1,         A + sa1 + k0, aok1);
        cp16(st + TILEB + so0, B + sb0 + k0, 16);
        cp16(st + TILEB + so1, B + sb1 + k0, 16);
        CP_COMMIT();
    };

    float acc[2][8][4];
    #pragma unroll
    for (int i = 0; i < 2; i++)
        #pragma unroll
        for (int j = 0; j < 8; j++)
            #pragma unroll
            for (int q = 0; q < 4; q++) acc[i][j][q] = 0.f;

    const uint32_t aob = (uint32_t)((wm * 32 + (lane & 15)) * ROWB + (lane >> 4) * 16);
    const uint32_t bob = (uint32_t)((wn * 64 + (lane & 7)) * ROWB + ((lane >> 3) & 1) * 16);

    issue(0);
    issue(1);
    for (int c = 0; c < NST; c++) {
        if (c + 1 < NST) CP_WAIT(1); else CP_WAIT(0);
        __syncthreads();
        if (c + 2 < NST) issue(c + 2);

        uint32_t st = sb + (uint32_t)(c % NBUF) * STAGEB;
        #pragma unroll
        for (int ks = 0; ks < 2; ks++) {
            uint32_t ao = st + aob + ks * 32;
            uint32_t bo = st + bob + ks * 32;
            uint32_t av[2][4];
            #pragma unroll
            for (int mt = 0; mt < 2; mt++)
                ldx4(av[mt], ao + mt * 16 * ROWB);
            #pragma unroll
            for (int nt = 0; nt < 8; nt++) {
                uint32_t bh[2];
                ldx2(bh, TILEB + bo + nt * 8 * ROWB);
                #pragma unroll
                for (int mt = 0; mt < 2; mt++)
                    mma16816h(acc[mt][nt], av[mt], bh);
            }
        }
    }

    const int g = lane >> 2, t2 = (lane & 3) * 2;
    #pragma unroll
    for (int mt = 0; mt < 2; mt++) {
        int r = row0 + wm * 32 + mt * 16 + g;
        #pragma unroll
        for (int nt = 0; nt < 8; nt++) {
            int col = col0 + wn * 64 + nt * 8 + t2;
            if (r < NN)
                *(half2*)(C + (size_t)r * DD + col) =
                    __floats2half2_rn(acc[mt][nt][0], acc[mt][nt][1]);
            if (r + 8 < NN)
                *(half2*)(C + (size_t)(r + 8) * DD + col) =
                    __floats2half2_rn(acc[mt][nt][2], acc[mt][nt][3]);
        }
    }
}

// ============================ edge aggregate: warp per node ============================
// Lane l owns columns [8l, 8l+8). Weights broadcast via shfl; rs accumulated
// identically on all lanes (no reduction). No smem, no block barriers.
__global__ void __launch_bounds__(256)
edge_agg(const float* __restrict__ nodes, float* __restrict__ out,
         const float* __restrict__ sqp, const float* __restrict__ snp,
         float* __restrict__ sn_out, const float* __restrict__ wa2n, int last) {
    const int node = blockIdx.x * 8 + (threadIdx.x >> 5);
    if (node >= NNODES) return;
    const int lane = threadIdx.x & 31;
    const int b = node / NN;
    const int off = g_eoff[node], end = g_eoff[node + 1];
    const float sq = sqp[node];
    const uint4* __restrict__ hb = (const uint4*)(g_h + (size_t)b * NN * DD);
    const float* __restrict__ snb = snp + b * NN;

    float acc[8];
    #pragma unroll
    for (int k = 0; k < 8; k++) acc[k] = 0.f;
    float rs = 0.f;

    for (int base = off; base < end; base += 32) {
        int m = min(32, end - base);
        int   dst_l = 0;
        float w_l = 0.f;
        if (lane < m) {
            dst_l = g_edst[base + lane];
            float s = sq + snb[dst_l];
            float lr = (s >= 0.f) ? s : ALPHA * s;
            w_l = __expf(-lr);
        }
        int e = 0;
        for (; e + 2 <= m; e += 2) {
            float w0 = __shfl_sync(0xFFFFFFFFu, w_l, e);
            float w1 = __shfl_sync(0xFFFFFFFFu, w_l, e + 1);
            int   d0 = __shfl_sync(0xFFFFFFFFu, dst_l, e);
            int   d1 = __shfl_sync(0xFFFFFFFFu, dst_l, e + 1);
            uint4 h0 = hb[(size_t)d0 * 32 + lane];
            uint4 h1 = hb[(size_t)d1 * 32 + lane];
            fma8(acc, h0, w0);
            fma8(acc, h1, w1);
            rs += w0 + w1;
        }
        if (e < m) {
            float w0 = __shfl_sync(0xFFFFFFFFu, w_l, e);
            int   d0 = __shfl_sync(0xFFFFFFFFu, dst_l, e);
            uint4 h0 = hb[(size_t)d0 * 32 + lane];
            fma8(acc, h0, w0);
            rs += w0;
        }
    }

    const float inv = (rs == 0.f) ? 0.f : 1.f / rs;
    float v[8];
    #pragma unroll
    for (int k = 0; k < 8; k++) v[k] = acc[k] * inv;

    const size_t base_idx = (size_t)node * DD + lane * 8;

    if (last) {
        float4 r0 = *(const float4*)(nodes + base_idx);
        float4 r1 = *(const float4*)(nodes + base_idx + 4);
        float4 o0 = make_float4(v[0] + r0.x, v[1] + r0.y, v[2] + r0.z, v[3] + r0.w);
        float4 o1 = make_float4(v[4] + r1.x, v[5] + r1.y, v[6] + r1.z, v[7] + r1.w);
        *(float4*)(out + base_idx)     = o0;
        *(float4*)(out + base_idx + 4) = o1;
    } else {
        __half hv[8];
        #pragma unroll
        for (int k = 0; k < 8; k++) hv[k] = __float2half_rn(v[k]);
        *(uint4*)(g_ah + base_idx) = *(uint4*)hv;
        // sn_next[node] = v . wa2_next (warp reduce)
        float p = 0.f;
        #pragma unroll
        for (int k = 0; k < 8; k++) p += v[k] * wa2n[lane * 8 + k];
        #pragma unroll
        for (int o = 16; o > 0; o >>= 1)
            p += __shfl_down_sync(0xFFFFFFFFu, p, o);
        if (lane == 0) sn_out[node] = p;
    }
}

// ---------------------------------------------------------------------------
extern "C" void kernel_launch(void* const* d_in, const int* in_sizes, int n_in,
                              void* d_out, int out_size) {
    const float* nodes  = (const float*)d_in[0];
    const float* nodesq = (const float*)d_in[1];
    const float* W      = (const float*)d_in[2];
    const float* a      = (const float*)d_in[3];
    const int*   edges  = (const int*)d_in[4];
    float* out = (float*)d_out;

    static cudaStream_t s1 = nullptr, s2 = nullptr;
    static cudaEvent_t evFork = nullptr, evW = nullptr, evScore = nullptr, evConv = nullptr;
    if (!s1) {
        cudaStreamCreateWithFlags(&s1, cudaStreamNonBlocking);
        cudaStreamCreateWithFlags(&s2, cudaStreamNonBlocking);
        cudaEventCreateWithFlags(&evFork,  cudaEventDisableTiming);
        cudaEventCreateWithFlags(&evW,     cudaEventDisableTiming);
        cudaEventCreateWithFlags(&evScore, cudaEventDisableTiming);
        cudaEventCreateWithFlags(&evConv,  cudaEventDisableTiming);
        cudaFuncSetAttribute(gemm_mma, cudaFuncAttributeMaxDynamicSharedMemorySize, SMEMB);
    }

    float *sqL, *snA, *snB, *wa2;
    int* degp;
    cudaGetSymbolAddress((void**)&sqL, g_sqL);
    cudaGetSymbolAddress((void**)&snA, g_snA);
    cudaGetSymbolAddress((void**)&snB, g_snB);
    cudaGetSymbolAddress((void**)&wa2, g_wa2);
    cudaGetSymbolAddress((void**)&degp, g_deg);

    dim3 ggrid(NTILES, DD / TN, NB);

    // ---- fork ----
    cudaEventRecord(evFork, 0);
    cudaStreamWaitEvent(s1, evFork, 0);
    cudaStreamWaitEvent(s2, evFork, 0);

    // s1: CSR build then scores
    cudaMemsetAsync(degp, 0, NNODES * sizeof(int), s1);
    hist<<<(NEDGES + 255) / 256, 256, 0, s1>>>(edges);
    scan_deg<<<1, 1024, 0, s1>>>();
    scatter<<<(NEDGES + 255) / 256, 256, 0, s1>>>(edges);

    // s2: activation conversion
    conv_half<<<(NB * NN * DD / 4 + 255) / 256, 256, 0, s2>>>(nodes);
    cudaEventRecord(evConv, s2);

    // main: wa -> (score dependency), prep_w
    wa_all<<<dim3(DD, 2), 256>>>(W, a);
    cudaEventRecord(evW, 0);
    prep_w<<<dim3(DD, 2), DD>>>(W);

    cudaStreamWaitEvent(s1, evW, 0);
    score_all<<<NNODES, 256, 0, s1>>>(nodesq, nodes);
    cudaEventRecord(evScore, s1);

    // ---- serial chain ----
    cudaStreamWaitEvent(0, evConv, 0);
    gemm_mma<<<ggrid, 256, SMEMB>>>(0);
    cudaStreamWaitEvent(0, evScore, 0);
    edge_agg<<<NNODES / 8, 256>>>(nodes, out, sqL, snA, snB, wa2 + DD, 0);
    gemm_mma<<<ggrid, 256, SMEMB>>>(1);
    edge_agg<<<NNODES / 8, 256>>>(nodes, out, sqL + NNODES, snB, nullptr, nullptr, 1);
}

// round 17
// speedup vs baseline: 1.6302x; 1.0698x over previous
#include <cuda_runtime.h>
#include <cuda_fp16.h>
#include <cstdint>

#define NB 2
#define NN 20000
#define DD 256
#define EE 320000
#define ALPHA 0.2f

#define TM 128
#define TN 128
#define KC 32
#define NST (DD / KC)                 // 8
#define NTILES ((NN + TM - 1) / TM)   // 157
#define ROWB 80                       // 64B data + 16B pad
#define TILEB (128 * ROWB)            // 10240
#define STAGEB (2 * TILEB)            // 20480 (A, B)
#define NBUF 3
#define SMEMB (NBUF * STAGEB)         // 61440 (3-stage)
#define NNODES (NB * NN)              // 40000
#define NEDGES (NB * EE)              // 640000

// ---------------- device scratch ----------------
__device__ __half g_h[NB * NN * DD];          // H = x @ Wc (fp16)
__device__ __half g_ah[NB * NN * DD];         // x fp16, later h1 fp16
__device__ __half g_wbh[DD * DD];             // Wc^T fp16 [n][k]
__device__ float g_wc[DD * DD];               // Wc fp32 [k][n]
__device__ float g_sqL[2 * NNODES];           // sq per layer
__device__ float g_snA[NNODES];               // sn0
__device__ float g_snB[NNODES];               // sn1 (from agg0)
__device__ float g_z[NNODES];                 // z = x . u
__device__ float g_wa1[2 * DD], g_wa2[2 * DD];
__device__ float g_u[DD];                     // u = W0 (W1 a2_1)
// CSR
__device__ int g_deg [NNODES];
__device__ int g_eoff[NNODES + 1];
__device__ int g_ecur[NNODES];
__device__ int g_edst[NEDGES];

// ---------------- helpers ----------------
__device__ __forceinline__ uint32_t smem_u32(const void* p) {
    uint32_t a;
    asm("{ .reg .u64 t; cvta.to.shared.u64 t, %1; cvt.u32.u64 %0, t; }" : "=r"(a) : "l"(p));
    return a;
}
__device__ __forceinline__ void cp16(uint32_t dst, const void* src, int bytes) {
    asm volatile("cp.async.cg.shared.global [%0], [%1], 16, %2;"
                 :: "r"(dst), "l"(src), "r"(bytes) : "memory");
}
#define CP_COMMIT() asm volatile("cp.async.commit_group;" ::: "memory")
#define CP_WAIT(n)  asm volatile("cp.async.wait_group %0;" :: "n"(n) : "memory")
__device__ __forceinline__ void ldx4(uint32_t r[4], uint32_t addr) {
    asm volatile("ldmatrix.sync.aligned.m8n8.x4.shared.b16 {%0,%1,%2,%3}, [%4];"
                 : "=r"(r[0]), "=r"(r[1]), "=r"(r[2]), "=r"(r[3]) : "r"(addr));
}
__device__ __forceinline__ void ldx2(uint32_t r[2], uint32_t addr) {
    asm volatile("ldmatrix.sync.aligned.m8n8.x2.shared.b16 {%0,%1}, [%2];"
                 : "=r"(r[0]), "=r"(r[1]) : "r"(addr));
}
__device__ __forceinline__ void mma16816h(float c[4], const uint32_t a[4], const uint32_t b[2]) {
    asm volatile("mma.sync.aligned.m16n8k16.row.col.f32.f16.f16.f32 "
                 "{%0,%1,%2,%3}, {%4,%5,%6,%7}, {%8,%9}, {%0,%1,%2,%3};"
                 : "+f"(c[0]), "+f"(c[1]), "+f"(c[2]), "+f"(c[3])
                 : "r"(a[0]), "r"(a[1]), "r"(a[2]), "r"(a[3]), "r"(b[0]), "r"(b[1]));
}
__device__ __forceinline__ void fma8(float acc[8], uint4 u, float w) {
    const half2* hp = (const half2*)&u;
    #pragma unroll
    for (int k = 0; k < 4; k++) {
        float2 f = __half22float2(hp[k]);
        acc[2 * k]     += w * f.x;
        acc[2 * k + 1] += w * f.y;
    }
}

// ============================ CSR construction ============================
__global__ void hist(const int* __restrict__ edges) {
    int i = blockIdx.x * blockDim.x + threadIdx.x;
    if (i >= NEDGES) return;
    int b = i / EE, e = i - b * EE;
    int src = edges[(size_t)b * 2 * EE + e];
    atomicAdd(&g_deg[b * NN + src], 1);
}
__global__ void scan_deg() {
    __shared__ int s[1024];
    const int base = threadIdx.x * 40;
    int loc[40];
    int run = 0;
    #pragma unroll
    for (int j = 0; j < 40; j++) {
        int i = base + j;
        int d = (i < NNODES) ? g_deg[i] : 0;
        run += d;
        loc[j] = run;
    }
    s[threadIdx.x] = run;
    __syncthreads();
    for (int o = 1; o < 1024; o <<= 1) {
        int add = (threadIdx.x >= o) ? s[threadIdx.x - o] : 0;
        __syncthreads();
        s[threadIdx.x] += add;
        __syncthreads();
    }
    int excl = threadIdx.x ? s[threadIdx.x - 1] : 0;
    int prev = excl;
    #pragma unroll
    for (int j = 0; j < 40; j++) {
        int i = base + j;
        if (i < NNODES) {
            g_ecur[i] = prev;
            g_eoff[i + 1] = excl + loc[j];
            prev = excl + loc[j];
        }
    }
    if (threadIdx.x == 0) g_eoff[0] = 0;
}
__global__ void scatter(const int* __restrict__ edges) {
    int i = blockIdx.x * blockDim.x + threadIdx.x;
    if (i >= NEDGES) return;
    int b = i / EE, e = i - b * EE;
    const int* eb = edges + (size_t)b * 2 * EE;
    int src = eb[e], dst = eb[EE + e];
    int pos = atomicAdd(&g_ecur[b * NN + src], 1);
    g_edst[pos] = dst;
}

// ============================ prep kernels ============================
__global__ void conv_half(const float* __restrict__ src) {
    int i = (blockIdx.x * blockDim.x + threadIdx.x) * 4;
    if (i >= NB * NN * DD) return;
    float4 v = *(const float4*)(src + i);
    __half h[4];
    h[0] = __float2half_rn(v.x); h[1] = __float2half_rn(v.y);
    h[2] = __float2half_rn(v.z); h[3] = __float2half_rn(v.w);
    *(uint2*)(g_ah + i) = *(uint2*)h;
}

__global__ void wa_all(const float* __restrict__ W, const float* __restrict__ a) {
    int k = blockIdx.x, l = blockIdx.y, t = threadIdx.x;
    const float* Wl = W + (size_t)l * DD * DD;
    const float* al = a + (size_t)l * 2 * DD;
    float w = Wl[k * DD + t];
    float v1 = w * al[t];
    float v2 = w * al[DD + t];
    #pragma unroll
    for (int o = 16; o > 0; o >>= 1) {
        v1 += __shfl_down_sync(0xFFFFFFFFu, v1, o);
        v2 += __shfl_down_sync(0xFFFFFFFFu, v2, o);
    }
    __shared__ float s1[8], s2[8];
    int wp = t >> 5, ln = t & 31;
    if (ln == 0) { s1[wp] = v1; s2[wp] = v2; }
    __syncthreads();
    if (t == 0) {
        float a1 = 0.f, a2 = 0.f;
        #pragma unroll
        for (int i = 0; i < 8; i++) { a1 += s1[i]; a2 += s2[i]; }
        g_wa1[l * DD + k] = a1;
        g_wa2[l * DD + k] = a2;
    }
}

// u[k] = sum_n W0[k][n] * wa2_1[n]
__global__ void u_vec(const float* __restrict__ W) {
    int k = blockIdx.x, t = threadIdx.x;
    float v = W[k * DD + t] * g_wa2[DD + t];
    #pragma unroll
    for (int o = 16; o > 0; o >>= 1)
        v += __shfl_down_sync(0xFFFFFFFFu, v, o);
    __shared__ float s[8];
    int wp = t >> 5, ln = t & 31;
    if (ln == 0) s[wp] = v;
    __syncthreads();
    if (t == 0) {
        float S = 0.f;
        #pragma unroll
        for (int i = 0; i < 8; i++) S += s[i];
        g_u[k] = S;
    }
}

// Wc[k][n] = sum_m W0[k][m] * W1[m][n]   (fp32, one block per k-row)
__global__ void wc_gemm(const float* __restrict__ W) {
    __shared__ float row[DD];
    const int k = blockIdx.x, t = threadIdx.x;
    const float* W0 = W;
    const float* W1 = W + DD * DD;
    row[t] = W0[k * DD + t];
    __syncthreads();
    float acc = 0.f;
    #pragma unroll 4
    for (int m = 0; m < DD; m++)
        acc += row[m] * W1[m * DD + t];
    g_wc[k * DD + t] = acc;
}

// g_wbh[n][k] = fp16(Wc[k][n])
__global__ void prep_w() {
    int n = blockIdx.x, k = threadIdx.x;
    g_wbh[n * DD + k] = __float2half_rn(g_wc[k * DD + n]);
}

// sq0, sq1 (from xq); sn0 = x.wa2_0; z = x.u
__global__ void score_all(const float* __restrict__ xq, const float* __restrict__ x0) {
    int node = blockIdx.x;
    int t = threadIdx.x;
    size_t idx = (size_t)node * DD + t;
    float q = xq[idx], x = x0[idx];
    float v0 = q * g_wa1[t];
    float v1 = q * g_wa1[DD + t];
    float v2 = x * g_wa2[t];
    float v3 = x * g_u[t];
    #pragma unroll
    for (int o = 16; o > 0; o >>= 1) {
        v0 += __shfl_down_sync(0xFFFFFFFFu, v0, o);
        v1 += __shfl_down_sync(0xFFFFFFFFu, v1, o);
        v2 += __shfl_down_sync(0xFFFFFFFFu, v2, o);
        v3 += __shfl_down_sync(0xFFFFFFFFu, v3, o);
    }
    __shared__ float s0[8], s1[8], s2[8], s3[8];
    int w = t >> 5, ln = t & 31;
    if (ln == 0) { s0[w] = v0; s1[w] = v1; s2[w] = v2; s3[w] = v3; }
    __syncthreads();
    if (t == 0) {
        float a0 = 0.f, a1 = 0.f, a2 = 0.f, a3 = 0.f;
        #pragma unroll
        for (int i = 0; i < 8; i++) { a0 += s0[i]; a1 += s1[i]; a2 += s2[i]; a3 += s3[i]; }
        g_sqL[node] = a0;
        g_sqL[NNODES + node] = a1;
        g_snA[node] = a2;
        g_z[node] = a3;
    }
}

// ============================ GEMM: H = x @ Wc (fp16, cp.async 3-stage) ============================
__global__ void __launch_bounds__(256, 2)
gemm_mma() {
    extern __shared__ char smem[];
    const int tid = threadIdx.x;
    const int wid = tid >> 5, lane = tid & 31;
    const int wm = wid & 3, wn = wid >> 2;

    const int b = blockIdx.z;
    const size_t boff = (size_t)b * NN * DD;
    const __half* A = g_ah + boff;
    const __half* B = g_wbh;
    __half* C = g_h + boff;
    const int row0 = blockIdx.x * TM;
    const int col0 = blockIdx.y * TN;

    const uint32_t sb = smem_u32(smem);

    const int crow0 = tid >> 2, cq0 = tid & 3;
    const int crow1 = (tid + 256) >> 2, cq1 = tid & 3;
    const int aok0 = (row0 + crow0) < NN ? 16 : 0;
    const int aok1 = (row0 + crow1) < NN ? 16 : 0;
    const uint32_t so0 = (uint32_t)(crow0 * ROWB + cq0 * 16);
    const uint32_t so1 = (uint32_t)(crow1 * ROWB + cq1 * 16);
    const size_t sa0 = (size_t)(row0 + crow0) * DD + cq0 * 8;
    const size_t sa1 = (size_t)(row0 + crow1) * DD + cq1 * 8;
    const size_t sb0 = (size_t)(col0 + crow0) * DD + cq0 * 8;
    const size_t sb1 = (size_t)(col0 + crow1) * DD + cq1 * 8;

    auto issue = [&](int c) {
        uint32_t st = sb + (uint32_t)(c % NBUF) * STAGEB;
        int k0 = c * KC;
        cp16(st + so0,         A + sa0 + k0, aok0);
        cp16(st + so1,         A + sa1 + k0, aok1);
        cp16(st + TILEB + so0, B + sb0 + k0, 16);
        cp16(st + TILEB + so1, B + sb1 + k0, 16);
        CP_COMMIT();
    };

    float acc[2][8][4];
    #pragma unroll
    for (int i = 0; i < 2; i++)
        #pragma unroll
        for (int j = 0; j < 8; j++)
            #pragma unroll
            for (int q = 0; q < 4; q++) acc[i][j][q] = 0.f;

    const uint32_t aob = (uint32_t)((wm * 32 + (lane & 15)) * ROWB + (lane >> 4) * 16);
    const uint32_t bob = (uint32_t)((wn * 64 + (lane & 7)) * ROWB + ((lane >> 3) & 1) * 16);

    issue(0);
    issue(1);
    for (int c = 0; c < NST; c++) {
        if (c + 1 < NST) CP_WAIT(1); else CP_WAIT(0);
        __syncthreads();
        if (c + 2 < NST) issue(c + 2);

        uint32_t st = sb + (uint32_t)(c % NBUF) * STAGEB;
        #pragma unroll
        for (int ks = 0; ks < 2; ks++) {
            uint32_t ao = st + aob + ks * 32;
            uint32_t bo = st + bob + ks * 32;
            uint32_t av[2][4];
            #pragma unroll
            for (int mt = 0; mt < 2; mt++)
                ldx4(av[mt], ao + mt * 16 * ROWB);
            #pragma unroll
            for (int nt = 0; nt < 8; nt++) {
                uint32_t bh[2];
                ldx2(bh, TILEB + bo + nt * 8 * ROWB);
                #pragma unroll
                for (int mt = 0; mt < 2; mt++)
                    mma16816h(acc[mt][nt], av[mt], bh);
            }
        }
    }

    const int g = lane >> 2, t2 = (lane & 3) * 2;
    #pragma unroll
    for (int mt = 0; mt < 2; mt++) {
        int r = row0 + wm * 32 + mt * 16 + g;
        #pragma unroll
        for (int nt = 0; nt < 8; nt++) {
            int col = col0 + wn * 64 + nt * 8 + t2;
            if (r < NN)
                *(half2*)(C + (size_t)r * DD + col) =
                    __floats2half2_rn(acc[mt][nt][0], acc[mt][nt][1]);
            if (r + 8 < NN)
                *(half2*)(C + (size_t)(r + 8) * DD + col) =
                    __floats2half2_rn(acc[mt][nt][2], acc[mt][nt][3]);
        }
    }
}

// ============================ edge aggregate: warp per node ============================
// mode last=0: hsrc=H, writes h1 (fp16 -> hout) and sn1 = agg(z)/rs -> sn_out
// mode last=1: hsrc=h1, writes out = v + nodes
__global__ void __launch_bounds__(256)
edge_agg(const __half* __restrict__ hsrc,
         const float* __restrict__ sqp, const float* __restrict__ snp,
         const float* __restrict__ zp,
         __half* __restrict__ hout, float* __restrict__ sn_out,
         const float* __restrict__ nodes, float* __restrict__ out, int last) {
    const int node = blockIdx.x * 8 + (threadIdx.x >> 5);
    if (node >= NNODES) return;
    const int lane = threadIdx.x & 31;
    const int b = node / NN;
    const int off = g_eoff[node], end = g_eoff[node + 1];
    const float sq = sqp[node];
    const uint4* __restrict__ hb = (const uint4*)(hsrc + (size_t)b * NN * DD);
    const float* __restrict__ snb = snp + b * NN;
    const float* __restrict__ zb = last ? nullptr : (zp + b * NN);

    float acc[8];
    #pragma unroll
    for (int k = 0; k < 8; k++) acc[k] = 0.f;
    float rs = 0.f;
    float zpart = 0.f;     // lane-partial sum of w*z

    for (int base = off; base < end; base += 32) {
        int m = min(32, end - base);
        int   dst_l = 0;
        float w_l = 0.f;
        if (lane < m) {
            dst_l = g_edst[base + lane];
            float s = sq + snb[dst_l];
            float lr = (s >= 0.f) ? s : ALPHA * s;
            w_l = __expf(-lr);
            if (!last) zpart += w_l * zb[dst_l];
        }
        int e = 0;
        for (; e + 2 <= m; e += 2) {
            float w0 = __shfl_sync(0xFFFFFFFFu, w_l, e);
            float w1 = __shfl_sync(0xFFFFFFFFu, w_l, e + 1);
            int   d0 = __shfl_sync(0xFFFFFFFFu, dst_l, e);
            int   d1 = __shfl_sync(0xFFFFFFFFu, dst_l, e + 1);
            uint4 h0 = hb[(size_t)d0 * 32 + lane];
            uint4 h1 = hb[(size_t)d1 * 32 + lane];
            fma8(acc, h0, w0);
            fma8(acc, h1, w1);
            rs += w0 + w1;
        }
        if (e < m) {
            float w0 = __shfl_sync(0xFFFFFFFFu, w_l, e);
            int   d0 = __shfl_sync(0xFFFFFFFFu, dst_l, e);
            uint4 h0 = hb[(size_t)d0 * 32 + lane];
            fma8(acc, h0, w0);
            rs += w0;
        }
    }

    const float inv = (rs == 0.f) ? 0.f : 1.f / rs;
    float v[8];
    #pragma unroll
    for (int k = 0; k < 8; k++) v[k] = acc[k] * inv;

    const size_t base_idx = (size_t)node * DD + lane * 8;

    if (last) {
        float4 r0 = *(const float4*)(nodes + base_idx);
        float4 r1 = *(const float4*)(nodes + base_idx + 4);
        float4 o0 = make_float4(v[0] + r0.x, v[1] + r0.y, v[2] + r0.z, v[3] + r0.w);
        float4 o1 = make_float4(v[4] + r1.x, v[5] + r1.y, v[6] + r1.z, v[7] + r1.w);
        *(float4*)(out + base_idx)     = o0;
        *(float4*)(out + base_idx + 4) = o1;
    } else {
        __half hv[8];
        #pragma unroll
        for (int k = 0; k < 8; k++) hv[k] = __float2half_rn(v[k]);
        *(uint4*)(hout + base_idx) = *(uint4*)hv;
        // sn1[node] = (sum w*z) / rs  (0 if rs==0)
        #pragma unroll
        for (int o = 16; o > 0; o >>= 1)
            zpart += __shfl_down_sync(0xFFFFFFFFu, zpart, o);
        if (lane == 0) sn_out[node] = zpart * inv;
    }
}

// ---------------------------------------------------------------------------
extern "C" void kernel_launch(void* const* d_in, const int* in_sizes, int n_in,
                              void* d_out, int out_size) {
    const float* nodes  = (const float*)d_in[0];
    const float* nodesq = (const float*)d_in[1];
    const float* W      = (const float*)d_in[2];
    const float* a      = (const float*)d_in[3];
    const int*   edges  = (const int*)d_in[4];
    float* out = (float*)d_out;

    static cudaStream_t s1 = nullptr, s2 = nullptr;
    static cudaEvent_t evFork = nullptr, evW = nullptr, evScore = nullptr, evConv = nullptr;
    if (!s1) {
        cudaStreamCreateWithFlags(&s1, cudaStreamNonBlocking);
        cudaStreamCreateWithFlags(&s2, cudaStreamNonBlocking);
        cudaEventCreateWithFlags(&evFork,  cudaEventDisableTiming);
        cudaEventCreateWithFlags(&evW,     cudaEventDisableTiming);
        cudaEventCreateWithFlags(&evScore, cudaEventDisableTiming);
        cudaEventCreateWithFlags(&evConv,  cudaEventDisableTiming);
        cudaFuncSetAttribute(gemm_mma, cudaFuncAttributeMaxDynamicSharedMemorySize, SMEMB);
    }

    float *sqL, *snA, *snB, *zp;
    __half *hp, *ahp;
    int* degp;
    cudaGetSymbolAddress((void**)&sqL, g_sqL);
    cudaGetSymbolAddress((void**)&snA, g_snA);
    cudaGetSymbolAddress((void**)&snB, g_snB);
    cudaGetSymbolAddress((void**)&zp,  g_z);
    cudaGetSymbolAddress((void**)&hp,  g_h);
    cudaGetSymbolAddress((void**)&ahp, g_ah);
    cudaGetSymbolAddress((void**)&degp, g_deg);

    dim3 ggrid(NTILES, DD / TN, NB);

    // ---- fork ----
    cudaEventRecord(evFork, 0);
    cudaStreamWaitEvent(s1, evFork, 0);
    cudaStreamWaitEvent(s2, evFork, 0);

    // s1: CSR build then scores
    cudaMemsetAsync(degp, 0, NNODES * sizeof(int), s1);
    hist<<<(NEDGES + 255) / 256, 256, 0, s1>>>(edges);
    scan_deg<<<1, 1024, 0, s1>>>();
    scatter<<<(NEDGES + 255) / 256, 256, 0, s1>>>(edges);

    // s2: activation conversion (x -> fp16)
    conv_half<<<(NB * NN * DD / 4 + 255) / 256, 256, 0, s2>>>(nodes);
    cudaEventRecord(evConv, s2);

    // main: wa vectors -> u -> (scores dependency); Wc = W0@W1 -> fp16 transpose
    wa_all<<<dim3(DD, 2), 256>>>(W, a);
    u_vec<<<DD, DD>>>(W);
    cudaEventRecord(evW, 0);
    wc_gemm<<<DD, DD>>>(W);
    prep_w<<<DD, DD>>>();

    cudaStreamWaitEvent(s1, evW, 0);
    score_all<<<NNODES, 256, 0, s1>>>(nodesq, nodes);
    cudaEventRecord(evScore, s1);

    // ---- serial chain: ONE gemm, two aggregations ----
    cudaStreamWaitEvent(0, evConv, 0);
    gemm_mma<<<ggrid, 256, SMEMB>>>();
    cudaStreamWaitEvent(0, evScore, 0);
    // agg0: H -> h1 (fp16 into g_ah), sn1 from z
    edge_agg<<<NNODES / 8, 256>>>(hp, sqL, snA, zp, ahp, snB, nullptr, nullptr, 0);
    // agg1: h1 -> out (+ residual)
    edge_agg<<<NNODES / 8, 256>>>(ahp, sqL + NNODES, snB, nullptr, nullptr, nullptr, nodes, out, 1);
}